// round 5
// baseline (speedup 1.0000x reference)
#include <cuda_runtime.h>
#include <cuda_bf16.h>
#include <math.h>
#include <stdint.h>

// LatticeMaxPooling (quincunx):
//   out0[i,j] = max(c0[i,j], c1[i,j], c0[i+1,j], c0[i,j+1], c0[i+1,j+1])
//   out1[i,j] = max(c1[i,j], c0[i+1,j+1], c1[i+1,j], c1[i,j+1], c1[i+1,j+1])
// Shapes: c0, c1 = [B=4, C=32, H=512, W=512] f32.  Output [2, B, C, H, W] f32.
// Strictly HBM-bound: ~512 MiB minimum traffic.

#define QP_W 512
#define QP_VPR 128            // vec4 slots per row
#define QP_THREADS 256

__device__ __forceinline__ float qp_max5(float a, float b, float c, float d, float e) {
    return fmaxf(fmaxf(fmaxf(a, b), fmaxf(c, d)), e);
}

template <bool VEC>
__global__ __launch_bounds__(QP_THREADS)
void LatticeMaxPooling_16853451669851_kernel(
    const float* __restrict__ c0,
    const float* __restrict__ c1,
    float* __restrict__ out,
    long long n_rows,     // total rows = B*C*H
    int H,                // rows per image (power of two)
    long long total)      // elements per coset = n_rows * 512
{
    const float NEGINF = -INFINITY;
    const long long n_work = n_rows * QP_VPR;
    const long long stride = (long long)gridDim.x * blockDim.x;
    const int hmask = H - 1;

    for (long long idx = (long long)blockIdx.x * blockDim.x + threadIdx.x;
         idx < n_work; idx += stride) {

        const long long row = idx >> 7;           // / QP_VPR
        const int t   = (int)(idx & (QP_VPR - 1));
        const int j0  = t * 4;
        const int i   = (int)row & hmask;         // row within one HxW image
        const long long base = row * QP_W;

        const bool has_e = (j0 + 4 < QP_W);
        const bool has_n = (i + 1 < H);

        float4 a0, b0, a1, b1;
        float a0e, b0e, a1e, b1e;

        if (VEC) {
            a0 = reinterpret_cast<const float4*>(c0 + base)[t];
            b0 = reinterpret_cast<const float4*>(c1 + base)[t];
        } else {
            a0 = make_float4(c0[base + j0], c0[base + j0 + 1], c0[base + j0 + 2], c0[base + j0 + 3]);
            b0 = make_float4(c1[base + j0], c1[base + j0 + 1], c1[base + j0 + 2], c1[base + j0 + 3]);
        }
        a0e = has_e ? c0[base + j0 + 4] : NEGINF;
        b0e = has_e ? c1[base + j0 + 4] : NEGINF;

        if (has_n) {
            const long long nb = base + QP_W;
            if (VEC) {
                a1 = reinterpret_cast<const float4*>(c0 + nb)[t];
                b1 = reinterpret_cast<const float4*>(c1 + nb)[t];
            } else {
                a1 = make_float4(c0[nb + j0], c0[nb + j0 + 1], c0[nb + j0 + 2], c0[nb + j0 + 3]);
                b1 = make_float4(c1[nb + j0], c1[nb + j0 + 1], c1[nb + j0 + 2], c1[nb + j0 + 3]);
            }
            a1e = has_e ? c0[nb + j0 + 4] : NEGINF;
            b1e = has_e ? c1[nb + j0 + 4] : NEGINF;
        } else {
            a1 = make_float4(NEGINF, NEGINF, NEGINF, NEGINF);
            b1 = a1;
            a1e = NEGINF;
            b1e = NEGINF;
        }

        // j+1 shifted views
        const float4 sa0 = make_float4(a0.y, a0.z, a0.w, a0e);
        const float4 sa1 = make_float4(a1.y, a1.z, a1.w, a1e);
        const float4 sb0 = make_float4(b0.y, b0.z, b0.w, b0e);
        const float4 sb1 = make_float4(b1.y, b1.z, b1.w, b1e);

        float4 o0, o1;
        o0.x = qp_max5(a0.x, b0.x, a1.x, sa0.x, sa1.x);
        o0.y = qp_max5(a0.y, b0.y, a1.y, sa0.y, sa1.y);
        o0.z = qp_max5(a0.z, b0.z, a1.z, sa0.z, sa1.z);
        o0.w = qp_max5(a0.w, b0.w, a1.w, sa0.w, sa1.w);

        o1.x = qp_max5(b0.x, sa1.x, b1.x, sb0.x, sb1.x);
        o1.y = qp_max5(b0.y, sa1.y, b1.y, sb0.y, sb1.y);
        o1.z = qp_max5(b0.z, sa1.z, b1.z, sb0.z, sb1.z);
        o1.w = qp_max5(b0.w, sa1.w, b1.w, sb0.w, sb1.w);

        if (VEC) {
            reinterpret_cast<float4*>(out + base)[t]         = o0;
            reinterpret_cast<float4*>(out + total + base)[t] = o1;
        } else {
            out[base + j0]     = o0.x;  out[base + j0 + 1] = o0.y;
            out[base + j0 + 2] = o0.z;  out[base + j0 + 3] = o0.w;
            out[total + base + j0]     = o1.x;  out[total + base + j0 + 1] = o1.y;
            out[total + base + j0 + 2] = o1.z;  out[total + base + j0 + 3] = o1.w;
        }
    }
}

extern "C" void kernel_launch(void* const* d_in, const int* in_sizes, int n_in,
                              void* d_out, int out_size) {
    const float* c0 = (const float*)d_in[0];
    const float* c1 = (const float*)d_in[1];
    float* out = (float*)d_out;

    // Be robust to units: take the smaller of the two size interpretations so
    // we can never address beyond the true allocation under either convention.
    long long t_in  = (long long)in_sizes[0];
    long long t_out = (long long)out_size / 2;
    long long total = (t_in < t_out) ? t_in : t_out;

    const int H = 512;
    const long long n_rows = total / QP_W;
    total = n_rows * QP_W;

    const long long n_work = n_rows * QP_VPR;
    int blocks = (int)((n_work + QP_THREADS - 1) / QP_THREADS);
    if (blocks < 1) blocks = 1;

    const bool aligned =
        ((uintptr_t)c0 % 16 == 0) && ((uintptr_t)c1 % 16 == 0) &&
        ((uintptr_t)out % 16 == 0) && ((total % 4) == 0);

    if (aligned) {
        LatticeMaxPooling_16853451669851_kernel<true><<<blocks, QP_THREADS>>>(
            c0, c1, out, n_rows, H, total);
    } else {
        LatticeMaxPooling_16853451669851_kernel<false><<<blocks, QP_THREADS>>>(
            c0, c1, out, n_rows, H, total);
    }
}

// round 6
// speedup vs baseline: 1.1227x; 1.1227x over previous
#include <cuda_runtime.h>
#include <cuda_bf16.h>
#include <math.h>
#include <stdint.h>

// LatticeMaxPooling (quincunx):
//   out0[i,j] = max(c0[i,j], c1[i,j], c0[i+1,j], c0[i,j+1], c0[i+1,j+1])
//   out1[i,j] = max(c1[i,j], c0[i+1,j+1], c1[i+1,j], c1[i,j+1], c1[i+1,j+1])
// [B=4, C=32, H=512, W=512] f32 per coset; output [2,B,C,H,W].
// HBM-bound: ~512 MiB min traffic. R5 profile showed L1tex (87%) binding, not
// DRAM (70%): the scalar j+1 edge loads double load wavefronts. This version
// gets the shift element via warp shuffle; only lane 31 loads from memory.

#define QP_W 512
#define QP_VPR 128            // vec4 slots per row
#define QP_THREADS 256

__device__ __forceinline__ float qp_max5(float a, float b, float c, float d, float e) {
    return fmaxf(fmaxf(fmaxf(a, b), fmaxf(c, d)), e);
}

__global__ __launch_bounds__(QP_THREADS)
void LatticeMaxPooling_vec_kernel(
    const float* __restrict__ c0,
    const float* __restrict__ c1,
    float* __restrict__ out,
    int n_rows,       // total rows = B*C*H
    int H,            // rows per image (power of two)
    int total)        // elements per coset = n_rows * 512  (fits int32)
{
    const float NEGINF = -INFINITY;
    const int n_work = n_rows * QP_VPR;
    const int stride = gridDim.x * blockDim.x;
    const int hmask = H - 1;
    const int lane = threadIdx.x & 31;
    const bool last_lane = (lane == 31);

    for (int idx = blockIdx.x * blockDim.x + threadIdx.x; idx < n_work; idx += stride) {
        const int row  = idx >> 7;                // / QP_VPR
        const int t    = idx & (QP_VPR - 1);
        const int i    = row & hmask;
        const int base = row * QP_W;
        const bool has_n = (i + 1 < H);
        const bool has_e = (t != QP_VPR - 1);     // j0+4 < 512

        // Vector loads: row i and i+1 of both cosets.
        float4 a0 = reinterpret_cast<const float4*>(c0 + base)[t];
        float4 b0 = reinterpret_cast<const float4*>(c1 + base)[t];
        float4 a1, b1;
        if (has_n) {
            a1 = reinterpret_cast<const float4*>(c0 + base + QP_W)[t];
            b1 = reinterpret_cast<const float4*>(c1 + base + QP_W)[t];
        } else {
            a1 = make_float4(NEGINF, NEGINF, NEGINF, NEGINF);
            b1 = a1;
        }

        // Warp-boundary element (j0+4) for lane 31 only: predicated scalar loads.
        float a0e_l = NEGINF, b0e_l = NEGINF, a1e_l = NEGINF, b1e_l = NEGINF;
        if (last_lane && has_e) {
            const int e = base + t * 4 + 4;
            a0e_l = c0[e];
            b0e_l = c1[e];
            if (has_n) {
                a1e_l = c0[e + QP_W];
                b1e_l = c1[e + QP_W];
            }
        }

        // Everyone else gets the shift tail from lane+1's .x via shuffle.
        float a0e = __shfl_down_sync(0xFFFFFFFFu, a0.x, 1);
        float b0e = __shfl_down_sync(0xFFFFFFFFu, b0.x, 1);
        float a1e = __shfl_down_sync(0xFFFFFFFFu, a1.x, 1);
        float b1e = __shfl_down_sync(0xFFFFFFFFu, b1.x, 1);
        if (last_lane) { a0e = a0e_l; b0e = b0e_l; a1e = a1e_l; b1e = b1e_l; }

        // j+1 shifted views
        const float4 sa0 = make_float4(a0.y, a0.z, a0.w, a0e);
        const float4 sa1 = make_float4(a1.y, a1.z, a1.w, a1e);
        const float4 sb0 = make_float4(b0.y, b0.z, b0.w, b0e);
        const float4 sb1 = make_float4(b1.y, b1.z, b1.w, b1e);

        float4 o0, o1;
        o0.x = qp_max5(a0.x, b0.x, a1.x, sa0.x, sa1.x);
        o0.y = qp_max5(a0.y, b0.y, a1.y, sa0.y, sa1.y);
        o0.z = qp_max5(a0.z, b0.z, a1.z, sa0.z, sa1.z);
        o0.w = qp_max5(a0.w, b0.w, a1.w, sa0.w, sa1.w);

        o1.x = qp_max5(b0.x, sa1.x, b1.x, sb0.x, sb1.x);
        o1.y = qp_max5(b0.y, sa1.y, b1.y, sb0.y, sb1.y);
        o1.z = qp_max5(b0.z, sa1.z, b1.z, sb0.z, sb1.z);
        o1.w = qp_max5(b0.w, sa1.w, b1.w, sb0.w, sb1.w);

        reinterpret_cast<float4*>(out + base)[t]         = o0;
        reinterpret_cast<float4*>(out + total + base)[t] = o1;
    }
}

// Fallback (unaligned pointers / odd sizes): scalar loads, no shuffle. Not
// expected to run on this problem, kept for safety.
__global__ __launch_bounds__(QP_THREADS)
void LatticeMaxPooling_scalar_kernel(
    const float* __restrict__ c0,
    const float* __restrict__ c1,
    float* __restrict__ out,
    long long n_rows, int H, long long total)
{
    const float NEGINF = -INFINITY;
    const long long n_work = n_rows * QP_W;
    const long long stride = (long long)gridDim.x * blockDim.x;
    for (long long idx = (long long)blockIdx.x * blockDim.x + threadIdx.x;
         idx < n_work; idx += stride) {
        const long long row = idx / QP_W;
        const int j = (int)(idx - row * QP_W);
        const int i = (int)(row % H);
        const long long base = row * QP_W;
        const bool he = (j + 1 < QP_W);
        const bool hn = (i + 1 < H);

        float a00 = c0[base + j];
        float b00 = c1[base + j];
        float a01 = he ? c0[base + j + 1] : NEGINF;
        float b01 = he ? c1[base + j + 1] : NEGINF;
        float a10 = hn ? c0[base + QP_W + j] : NEGINF;
        float b10 = hn ? c1[base + QP_W + j] : NEGINF;
        float a11 = (hn && he) ? c0[base + QP_W + j + 1] : NEGINF;
        float b11 = (hn && he) ? c1[base + QP_W + j + 1] : NEGINF;

        out[base + j]         = qp_max5(a00, b00, a10, a01, a11);
        out[total + base + j] = qp_max5(b00, a11, b10, b01, b11);
    }
}

extern "C" void kernel_launch(void* const* d_in, const int* in_sizes, int n_in,
                              void* d_out, int out_size) {
    const float* c0 = (const float*)d_in[0];
    const float* c1 = (const float*)d_in[1];
    float* out = (float*)d_out;

    long long t_in  = (long long)in_sizes[0];
    long long t_out = (long long)out_size / 2;
    long long total = (t_in < t_out) ? t_in : t_out;

    const int H = 512;
    const long long n_rows = total / QP_W;
    total = n_rows * QP_W;

    const bool aligned =
        ((uintptr_t)c0 % 16 == 0) && ((uintptr_t)c1 % 16 == 0) &&
        ((uintptr_t)out % 16 == 0) &&
        (2 * total < 0x7FFFFFFFLL);           // int32-indexable

    if (aligned) {
        const int n_work = (int)(n_rows * QP_VPR);
        int blocks = (n_work + QP_THREADS - 1) / QP_THREADS;
        if (blocks < 1) blocks = 1;
        LatticeMaxPooling_vec_kernel<<<blocks, QP_THREADS>>>(
            c0, c1, out, (int)n_rows, H, (int)total);
    } else {
        const long long n_work = n_rows * QP_W;
        int blocks = (int)((n_work + QP_THREADS - 1) / QP_THREADS);
        if (blocks < 1) blocks = 1;
        LatticeMaxPooling_scalar_kernel<<<blocks, QP_THREADS>>>(
            c0, c1, out, n_rows, H, total);
    }
}